// round 4
// baseline (speedup 1.0000x reference)
#include <cuda_runtime.h>
#include <cuda_bf16.h>

// LengthRegulator: out[b,t,:] = x[b, searchsorted(cumsum(dur[b]), t, 'right'), :]
// (zeros for t >= total duration). Shapes fixed by the problem:
//   x: [16, 512, 512] f32, durations: [16, 512] i32, out: [16, 4096, 512] f32.
//
// Token-centric formulation: token j owns the contiguous output span
// [cum[j-1], min(cum[j], T)). One warp per token reads the 2KB x row ONCE
// (minimum possible read traffic) and streams contiguous 2KB stores.

static constexpr int B  = 16;
static constexpr int S  = 512;
static constexpr int H  = 512;
static constexpr int T  = 4096;
static constexpr int H4 = H / 4;          // 128 float4 per row
static constexpr int ZW = 128;            // zero-fill warps per batch

// Per-token exclusive start offset, and per-batch total duration.
__device__ int g_start[B * S];
__device__ int g_total[B];

// One block per batch: warp-shuffle inclusive scan of durations; emit
// exclusive starts and the batch total. No per-frame work at all.
__global__ void scan_kernel(const int* __restrict__ durations) {
    __shared__ int warp_sums[16];
    const int b    = blockIdx.x;
    const int tid  = threadIdx.x;         // blockDim.x == S == 512
    const int lane = tid & 31;
    const int wid  = tid >> 5;            // 16 warps

    const int d = durations[b * S + tid];

    int v = d;
    #pragma unroll
    for (int off = 1; off < 32; off <<= 1) {
        int n = __shfl_up_sync(0xffffffffu, v, off);
        if (lane >= off) v += n;
    }
    if (lane == 31) warp_sums[wid] = v;
    __syncthreads();

    if (wid == 0 && lane < 16) {
        int w = warp_sums[lane];
        #pragma unroll
        for (int off = 1; off < 16; off <<= 1) {
            int n = __shfl_up_sync(0xffffu, w, off);
            if (lane >= off) w += n;
        }
        warp_sums[lane] = w;
    }
    __syncthreads();

    const int cum = v + (wid > 0 ? warp_sums[wid - 1] : 0);  // inclusive
    g_start[b * S + tid] = cum - d;                           // exclusive
    if (tid == S - 1) g_total[b] = cum;
}

// Warps [0, B*S): token copy warps. Warps [B*S, B*S + B*ZW): zero-tail warps.
__global__ void expand_kernel(const float4* __restrict__ x,
                              const int* __restrict__ durations,
                              float4* __restrict__ out) {
    const int w    = blockIdx.x * (blockDim.x >> 5) + (threadIdx.x >> 5);
    const int lane = threadIdx.x & 31;

    if (w < B * S) {
        // ── Token copy: read row once, stream dur contiguous 2KB stores.
        const int b   = w >> 9;           // / S
        const int j   = w & (S - 1);
        const int dur = durations[w];
        if (dur == 0) return;
        const int start = g_start[w];
        int end = start + dur;
        if (end > T) end = T;
        if (start >= end) return;

        const float4* src = x + ((long long)w << 7);   // x[b, j, :]
        const float4 v0 = src[lane];
        const float4 v1 = src[lane + 32];
        const float4 v2 = src[lane + 64];
        const float4 v3 = src[lane + 96];

        float4* o = out + ((long long)((b << 12) + start) << 7);
        for (int t = start; t < end; ++t, o += H4) {
            o[lane]      = v0;
            o[lane + 32] = v1;
            o[lane + 64] = v2;
            o[lane + 96] = v3;
        }
    } else {
        // ── Zero tail: frames [total, T) of batch b, ZW warps interleaved.
        const int z = w - B * S;
        const int b = z >> 7;             // / ZW
        const int k = z & (ZW - 1);
        const int total = g_total[b];
        const float4 zero = make_float4(0.f, 0.f, 0.f, 0.f);
        for (int t = total + k; t < T; t += ZW) {
            float4* o = out + ((long long)((b << 12) + t) << 7);
            o[lane]      = zero;
            o[lane + 32] = zero;
            o[lane + 64] = zero;
            o[lane + 96] = zero;
        }
    }
}

extern "C" void kernel_launch(void* const* d_in, const int* in_sizes, int n_in,
                              void* d_out, int out_size) {
    const float* x   = (const float*)d_in[0];      // [B, S, H] f32
    const int*   dur = (const int*)d_in[1];        // [B, S]   i32
    float*       out = (float*)d_out;              // [B, T, H] f32
    (void)in_sizes; (void)n_in; (void)out_size;

    scan_kernel<<<B, S>>>(dur);

    const int threads = 256;                       // 8 warps per block
    const int total_warps = B * S + B * ZW;        // 8192 + 2048 = 10240
    const int blocks = total_warps / (threads / 32);  // 1280
    expand_kernel<<<blocks, threads>>>((const float4*)x, dur, (float4*)out);
}